// round 1
// baseline (speedup 1.0000x reference)
#include <cuda_runtime.h>

#define L   1024
#define D   512
#define H   8
#define HD  64
#define EPSF 1e-5f

// ---------------- scratch (device globals; no allocation) ----------------
__device__ float g_q [H*L*HD];
__device__ float g_k [H*L*HD];
__device__ float g_v [H*L*HD];
__device__ float g_kc[H*L*HD];
__device__ float g_vc[H*L*HD];
__device__ float g_gate[H*L];
__device__ float g_gcum[H*L];
__device__ float g_unit[L*D];

// ---------------- shared 64x64x(K) GEMM core: C_tile = A @ B^T ----------
// A: [M,K] row-major, B: [N,K] row-major. BM=BN=64, BK=16, 256 threads,
// 4x4 register tile per thread. As/Bs are k-major with stride 68 (pad).
__device__ __forceinline__ void gemm_acc(const float* __restrict__ A,
                                         const float* __restrict__ B,
                                         int m0, int n0, int K,
                                         float acc[4][4],
                                         float* As, float* Bs)
{
    const int tid = threadIdx.x;
    const int tx = tid & 15, ty = tid >> 4;
    for (int k0 = 0; k0 < K; k0 += 16) {
        const int mr = tid >> 2;
        const int kq = (tid & 3) << 2;
        float4 av = *(const float4*)(A + (m0 + mr) * K + k0 + kq);
        As[(kq+0)*68 + mr] = av.x;
        As[(kq+1)*68 + mr] = av.y;
        As[(kq+2)*68 + mr] = av.z;
        As[(kq+3)*68 + mr] = av.w;
        float4 bv = *(const float4*)(B + (n0 + mr) * K + k0 + kq);
        Bs[(kq+0)*68 + mr] = bv.x;
        Bs[(kq+1)*68 + mr] = bv.y;
        Bs[(kq+2)*68 + mr] = bv.z;
        Bs[(kq+3)*68 + mr] = bv.w;
        __syncthreads();
        #pragma unroll
        for (int kk = 0; kk < 16; kk++) {
            float4 a4 = *(const float4*)(As + kk*68 + (ty<<2));
            float4 b4 = *(const float4*)(Bs + kk*68 + (tx<<2));
            float a[4] = {a4.x, a4.y, a4.z, a4.w};
            float b[4] = {b4.x, b4.y, b4.z, b4.w};
            #pragma unroll
            for (int i = 0; i < 4; i++)
                #pragma unroll
                for (int j = 0; j < 4; j++)
                    acc[i][j] += a[i] * b[j];
        }
        __syncthreads();
    }
}

// ---------------- kernel 1: fused QKV projections ------------------------
// grid (8, 16, 3): x -> q/k/v in head-major [H][L][64] layout; k scaled h^-0.5.
__global__ void qkv_kernel(const float* __restrict__ x,
                           const float* __restrict__ wq, const float* __restrict__ bq,
                           const float* __restrict__ wk, const float* __restrict__ bk,
                           const float* __restrict__ wv, const float* __restrict__ bv)
{
    __shared__ float As[16*68];
    __shared__ float Bs[16*68];
    const int z = blockIdx.z;
    const float* W    = (z == 0) ? wq : (z == 1) ? wk : wv;
    const float* bias = (z == 0) ? bq : (z == 1) ? bk : bv;
    float* out        = (z == 0) ? g_q : (z == 1) ? g_k : g_v;
    const float scale = (z == 1) ? 0.125f : 1.0f;   // h^-0.5, h=64

    const int m0 = blockIdx.y * 64;
    const int n0 = blockIdx.x * 64;
    const int head = blockIdx.x;                     // 64-wide heads align with BN

    float acc[4][4] = {};
    gemm_acc(x, W, m0, n0, D, acc, As, Bs);

    const int tx = threadIdx.x & 15, ty = threadIdx.x >> 4;
    #pragma unroll
    for (int i = 0; i < 4; i++) {
        const int m = m0 + (ty<<2) + i;
        float4 o;
        o.x = (acc[i][0] + bias[n0 + (tx<<2) + 0]) * scale;
        o.y = (acc[i][1] + bias[n0 + (tx<<2) + 1]) * scale;
        o.z = (acc[i][2] + bias[n0 + (tx<<2) + 2]) * scale;
        o.w = (acc[i][3] + bias[n0 + (tx<<2) + 3]) * scale;
        *(float4*)(out + (head * L + m) * HD + (tx<<2)) = o;
    }
}

// ---------------- kernel 2: causal Toeplitz conv (k_conv, v_conv) --------
// out[l,d] = sum_{s<=l} phi[l-s, head] * in[s,d]. grid (H, L/64, 2).
__global__ void conv_kernel(const float* __restrict__ phi)
{
    __shared__ float Ks[64*64];
    __shared__ float ph[128];
    const int head = blockIdx.x;
    const int lb   = blockIdx.y;
    const int z    = blockIdx.z;
    const float* src = (z ? g_v : g_k) + head * L * HD;
    float* dst       = (z ? g_vc : g_kc) + head * L * HD;

    const int tid = threadIdx.x;
    const int tx = tid & 15, ty = tid >> 4;
    const int l0 = lb * 64;
    float acc[4][4] = {};

    for (int sb = 0; sb <= lb; sb++) {
        const int s0 = sb * 64;
        // load K tile [64 s][64 d], coalesced float4
        #pragma unroll
        for (int rep = 0; rep < 4; rep++) {
            const int g  = tid + rep * 256;
            const int r  = g >> 4;
            const int c4 = (g & 15) << 2;
            *(float4*)(Ks + r*64 + c4) = *(const float4*)(src + (s0 + r) * HD + c4);
        }
        // load phi segment: offsets base..base+126 where base = l0-s0-63
        if (tid < 127) {
            const int off = l0 - s0 - 63 + tid;
            ph[tid] = (off >= 0) ? phi[off * H + head] : 0.0f;
        }
        __syncthreads();

        if (sb < lb) {
            #pragma unroll 4
            for (int s = 0; s < 64; s++) {
                float4 b4 = *(const float4*)(Ks + s*64 + (tx<<2));
                float b[4] = {b4.x, b4.y, b4.z, b4.w};
                #pragma unroll
                for (int i = 0; i < 4; i++) {
                    const float a = ph[63 + (ty<<2) + i - s];
                    #pragma unroll
                    for (int j = 0; j < 4; j++) acc[i][j] += a * b[j];
                }
            }
        } else {  // diagonal tile: causal mask l >= s
            #pragma unroll 4
            for (int s = 0; s < 64; s++) {
                float4 b4 = *(const float4*)(Ks + s*64 + (tx<<2));
                float b[4] = {b4.x, b4.y, b4.z, b4.w};
                #pragma unroll
                for (int i = 0; i < 4; i++) {
                    const int ll = (ty<<2) + i;
                    const float pv = ph[63 + ll - s];
                    const float a = (ll >= s) ? pv : 0.0f;
                    #pragma unroll
                    for (int j = 0; j < 4; j++) acc[i][j] += a * b[j];
                }
            }
        }
        __syncthreads();
    }

    #pragma unroll
    for (int i = 0; i < 4; i++) {
        float4 o = make_float4(acc[i][0], acc[i][1], acc[i][2], acc[i][3]);
        *(float4*)(dst + (l0 + (ty<<2) + i) * HD + (tx<<2)) = o;
    }
}

// ---------------- kernel 3: gates g = relu(v_c^T W k_c + b)^2 + eps ------
// one warp per (head, l). W transposed in smem for conflict-free reads.
__global__ void gate_kernel(const float* __restrict__ wg,
                            const float* __restrict__ wgb)
{
    __shared__ float wgT[64*64];   // wgT[n][m] = wg[m*64+n]
    const int tid = threadIdx.x;
    #pragma unroll
    for (int r = 0; r < 16; r++) {
        const int idx = tid + r * 256;
        const int m = idx >> 6, n = idx & 63;
        wgT[n * 64 + m] = wg[idx];
    }
    __syncthreads();

    const int warp = tid >> 5, lane = tid & 31;
    const int gidx = blockIdx.x * 8 + warp;      // = head*L + l
    const float* kc = g_kc + gidx * HD;
    const float* vc = g_vc + gidx * HD;

    float sum = 0.0f;
    #pragma unroll
    for (int half = 0; half < 2; half++) {
        const int m = lane + half * 32;
        float inner = 0.0f;
        #pragma unroll 8
        for (int n = 0; n < 64; n++)
            inner += wgT[n * 64 + m] * kc[n];
        sum += vc[m] * inner;
    }
    #pragma unroll
    for (int o = 16; o; o >>= 1) sum += __shfl_xor_sync(0xffffffffu, sum, o);

    if (lane == 0) {
        const float r = fmaxf(sum + wgb[0], 0.0f);
        g_gate[gidx] = r * r + EPSF;
    }
}

// ---------------- kernel 4: inclusive prefix sum of gates per head -------
__global__ void scan_kernel()
{
    __shared__ float s[L];
    const int head = blockIdx.x, t = threadIdx.x;
    s[t] = g_gate[head * L + t];
    __syncthreads();
    for (int off = 1; off < L; off <<= 1) {
        const float v = (t >= off) ? s[t - off] : 0.0f;
        __syncthreads();
        s[t] += v;
        __syncthreads();
    }
    g_gcum[head * L + t] = s[t];
}

// ---------------- kernel 5: causal linear attention + normalize ----------
// ctxt[l] = (1/(G_l+eps)) * sum_{s<=l} g_s (q_l . v_c[s]) k_c[s]; then L2-norm.
// grid (H, L/64), 256 threads, smem = exactly 48KB.
__global__ void attn_kernel()
{
    __shared__ float QsT[64*64];   // Q transposed: [d][l]
    __shared__ float Ts [64*64];   // per s-tile: (g*Vc)^T [d][s], then Kc [s][d]
    __shared__ float Ps [64*64];   // P[l][s]; later C[l][d]

    const int head = blockIdx.x, lb = blockIdx.y;
    const int l0 = lb * 64;
    const float* qh  = g_q  + head * L * HD;
    const float* kch = g_kc + head * L * HD;
    const float* vch = g_vc + head * L * HD;
    const float* gh  = g_gate + head * L;

    const int tid = threadIdx.x;
    const int tx = tid & 15, ty = tid >> 4;

    // load Q tile transposed
    #pragma unroll
    for (int rep = 0; rep < 4; rep++) {
        const int g  = tid + rep * 256;
        const int r  = g >> 4;            // l (local)
        const int c4 = (g & 15) << 2;     // d
        float4 v = *(const float4*)(qh + (l0 + r) * HD + c4);
        QsT[(c4+0)*64 + r] = v.x;
        QsT[(c4+1)*64 + r] = v.y;
        QsT[(c4+2)*64 + r] = v.z;
        QsT[(c4+3)*64 + r] = v.w;
    }

    float acc[4][4] = {};
    for (int sb = 0; sb <= lb; sb++) {
        const int s0 = sb * 64;
        __syncthreads();                   // Ts free from previous iteration
        // load (g * Vc) transposed into Ts
        #pragma unroll
        for (int rep = 0; rep < 4; rep++) {
            const int g  = tid + rep * 256;
            const int r  = g >> 4;         // s (local)
            const int c4 = (g & 15) << 2;  // d
            const float gs = gh[s0 + r];
            float4 v = *(const float4*)(vch + (s0 + r) * HD + c4);
            Ts[(c4+0)*64 + r] = v.x * gs;
            Ts[(c4+1)*64 + r] = v.y * gs;
            Ts[(c4+2)*64 + r] = v.z * gs;
            Ts[(c4+3)*64 + r] = v.w * gs;
        }
        __syncthreads();

        // stage 1: P[l][s] = sum_d Q[l][d] * gV[s][d]
        float pacc[4][4] = {};
        #pragma unroll 4
        for (int dd = 0; dd < 64; dd++) {
            float4 a4 = *(const float4*)(QsT + dd*64 + (ty<<2));
            float4 b4 = *(const float4*)(Ts  + dd*64 + (tx<<2));
            float a[4] = {a4.x, a4.y, a4.z, a4.w};
            float b[4] = {b4.x, b4.y, b4.z, b4.w};
            #pragma unroll
            for (int i = 0; i < 4; i++)
                #pragma unroll
                for (int j = 0; j < 4; j++)
                    pacc[i][j] += a[i] * b[j];
        }
        if (sb == lb) {                    // causal mask on diagonal tile
            #pragma unroll
            for (int i = 0; i < 4; i++)
                #pragma unroll
                for (int j = 0; j < 4; j++)
                    if ((tx<<2) + j > (ty<<2) + i) pacc[i][j] = 0.0f;
        }
        #pragma unroll
        for (int i = 0; i < 4; i++)
            *(float4*)(Ps + ((ty<<2)+i)*64 + (tx<<2)) =
                make_float4(pacc[i][0], pacc[i][1], pacc[i][2], pacc[i][3]);
        __syncthreads();

        // load Kc tile (normal layout) into Ts
        #pragma unroll
        for (int rep = 0; rep < 4; rep++) {
            const int g  = tid + rep * 256;
            const int r  = g >> 4;
            const int c4 = (g & 15) << 2;
            *(float4*)(Ts + r*64 + c4) = *(const float4*)(kch + (s0 + r) * HD + c4);
        }
        __syncthreads();

        // stage 2: O[l][o] += sum_s P[l][s] * Kc[s][o]
        #pragma unroll 4
        for (int s = 0; s < 64; s++) {
            float a[4];
            #pragma unroll
            for (int i = 0; i < 4; i++) a[i] = Ps[((ty<<2)+i)*64 + s];
            float4 b4 = *(const float4*)(Ts + s*64 + (tx<<2));
            float b[4] = {b4.x, b4.y, b4.z, b4.w};
            #pragma unroll
            for (int i = 0; i < 4; i++)
                #pragma unroll
                for (int j = 0; j < 4; j++)
                    acc[i][j] += a[i] * b[j];
        }
    }
    __syncthreads();

    // epilogue: ctxt = O/(G+eps); L2-normalize rows; write to g_unit
    #pragma unroll
    for (int i = 0; i < 4; i++) {
        const float G = g_gcum[head * L + l0 + (ty<<2) + i];
        const float gi = 1.0f / (G + EPSF);
        #pragma unroll
        for (int j = 0; j < 4; j++) acc[i][j] *= gi;
        *(float4*)(Ps + ((ty<<2)+i)*64 + (tx<<2)) =
            make_float4(acc[i][0], acc[i][1], acc[i][2], acc[i][3]);
    }
    __syncthreads();

    float* rnorm = Ts;                     // reuse
    if (tid < 64) {
        float ss = 0.0f;
        #pragma unroll 8
        for (int d2 = 0; d2 < 64; d2++) {
            const float c = Ps[tid*64 + d2];
            ss += c * c;
        }
        rnorm[tid] = fmaxf(sqrtf(ss), EPSF);
    }
    __syncthreads();

    #pragma unroll
    for (int i = 0; i < 4; i++) {
        const float ri = 1.0f / rnorm[(ty<<2) + i];
        float4 o = make_float4(acc[i][0]*ri, acc[i][1]*ri, acc[i][2]*ri, acc[i][3]*ri);
        *(float4*)(g_unit + (l0 + (ty<<2) + i) * D + head * HD + (tx<<2)) = o;
    }
}

// ---------------- kernel 6: output projection ----------------------------
__global__ void oproj_kernel(const float* __restrict__ wo,
                             const float* __restrict__ bo,
                             float* __restrict__ out)
{
    __shared__ float As[16*68];
    __shared__ float Bs[16*68];
    const int m0 = blockIdx.y * 64;
    const int n0 = blockIdx.x * 64;
    float acc[4][4] = {};
    gemm_acc(g_unit, wo, m0, n0, D, acc, As, Bs);

    const int tx = threadIdx.x & 15, ty = threadIdx.x >> 4;
    #pragma unroll
    for (int i = 0; i < 4; i++) {
        const int m = m0 + (ty<<2) + i;
        float4 o;
        o.x = acc[i][0] + bo[n0 + (tx<<2) + 0];
        o.y = acc[i][1] + bo[n0 + (tx<<2) + 1];
        o.z = acc[i][2] + bo[n0 + (tx<<2) + 2];
        o.w = acc[i][3] + bo[n0 + (tx<<2) + 3];
        *(float4*)(out + m * D + n0 + (tx<<2)) = o;
    }
}

// ---------------- launch --------------------------------------------------
extern "C" void kernel_launch(void* const* d_in, const int* in_sizes, int n_in,
                              void* d_out, int out_size)
{
    const float* x   = (const float*)d_in[0];
    const float* phi = (const float*)d_in[1];
    const float* wq  = (const float*)d_in[2];
    const float* bq  = (const float*)d_in[3];
    const float* wk  = (const float*)d_in[4];
    const float* bk  = (const float*)d_in[5];
    const float* wv  = (const float*)d_in[6];
    const float* bv  = (const float*)d_in[7];
    const float* wo  = (const float*)d_in[8];
    const float* bo  = (const float*)d_in[9];
    const float* wg  = (const float*)d_in[10];
    const float* wgb = (const float*)d_in[11];
    float* out = (float*)d_out;

    qkv_kernel <<<dim3(8, 16, 3), 256>>>(x, wq, bq, wk, bk, wv, bv);
    conv_kernel<<<dim3(8, 16, 2), 256>>>(phi);
    gate_kernel<<<1024, 256>>>(wg, wgb);
    scan_kernel<<<8, 1024>>>();
    attn_kernel<<<dim3(8, 16), 256>>>();
    oproj_kernel<<<dim3(8, 16), 256>>>(wo, bo, out);
}

// round 5
// speedup vs baseline: 1.2328x; 1.2328x over previous
#include <cuda_runtime.h>

#define L   1024
#define D   512
#define H   8
#define HD  64
#define EPSF 1e-5f
#define SZ  (H*L*HD)          // 524288 elems per [H][L][HD] tensor

// ---------------- scratch (device globals; no allocation) ----------------
__device__ float g_q [SZ];
__device__ float g_k [SZ];
__device__ float g_v [SZ];
__device__ float g_kc[SZ];
__device__ float g_vc[SZ];
__device__ float g_gate[H*L];
__device__ float g_gcum[H*L];
__device__ float g_unit[L*D];
__device__ float g_cpart[2*4*SZ];   // conv partials: [z][chunk][H][L][HD]
__device__ float g_opart[4*SZ];     // attn partials: [chunk][H][L][HD]

// Balanced triangular task map: 40 tasks per head, each <=4 s-tiles.
// task t -> (lb, chunk): group g = floor-range; lb = g*4 + idx/(g+1); ch = idx%(g+1)
__device__ __forceinline__ void task_map(int t, int& lb, int& ch)
{
    int g, base;
    if      (t < 4)  { g = 0; base = 0;  }
    else if (t < 12) { g = 1; base = 4;  }
    else if (t < 24) { g = 2; base = 12; }
    else             { g = 3; base = 24; }
    const int idx = t - base;
    lb = g * 4 + idx / (g + 1);
    ch = idx % (g + 1);
}

// ---------------- shared 64x64x(K) GEMM core: C_tile = A @ B^T ----------
__device__ __forceinline__ void gemm_acc(const float* __restrict__ A,
                                         const float* __restrict__ B,
                                         int m0, int n0, int K,
                                         float acc[4][4],
                                         float* As, float* Bs)
{
    const int tid = threadIdx.x;
    const int tx = tid & 15, ty = tid >> 4;
    for (int k0 = 0; k0 < K; k0 += 16) {
        const int mr = tid >> 2;
        const int kq = (tid & 3) << 2;
        float4 av = *(const float4*)(A + (m0 + mr) * K + k0 + kq);
        As[(kq+0)*68 + mr] = av.x;
        As[(kq+1)*68 + mr] = av.y;
        As[(kq+2)*68 + mr] = av.z;
        As[(kq+3)*68 + mr] = av.w;
        float4 bv = *(const float4*)(B + (n0 + mr) * K + k0 + kq);
        Bs[(kq+0)*68 + mr] = bv.x;
        Bs[(kq+1)*68 + mr] = bv.y;
        Bs[(kq+2)*68 + mr] = bv.z;
        Bs[(kq+3)*68 + mr] = bv.w;
        __syncthreads();
        #pragma unroll
        for (int kk = 0; kk < 16; kk++) {
            float4 a4 = *(const float4*)(As + kk*68 + (ty<<2));
            float4 b4 = *(const float4*)(Bs + kk*68 + (tx<<2));
            float a[4] = {a4.x, a4.y, a4.z, a4.w};
            float b[4] = {b4.x, b4.y, b4.z, b4.w};
            #pragma unroll
            for (int i = 0; i < 4; i++)
                #pragma unroll
                for (int j = 0; j < 4; j++)
                    acc[i][j] += a[i] * b[j];
        }
        __syncthreads();
    }
}

// ---------------- kernel 1: fused QKV projections ------------------------
__global__ void __launch_bounds__(256)
qkv_kernel(const float* __restrict__ x,
           const float* __restrict__ wq, const float* __restrict__ bq,
           const float* __restrict__ wk, const float* __restrict__ bk,
           const float* __restrict__ wv, const float* __restrict__ bv)
{
    __shared__ float As[16*68];
    __shared__ float Bs[16*68];
    const int z = blockIdx.z;
    const float* W    = (z == 0) ? wq : (z == 1) ? wk : wv;
    const float* bias = (z == 0) ? bq : (z == 1) ? bk : bv;
    float* out        = (z == 0) ? g_q : (z == 1) ? g_k : g_v;
    const float scale = (z == 1) ? 0.125f : 1.0f;   // h^-0.5, h=64

    const int m0 = blockIdx.y * 64;
    const int n0 = blockIdx.x * 64;
    const int head = blockIdx.x;

    float acc[4][4] = {};
    gemm_acc(x, W, m0, n0, D, acc, As, Bs);

    const int tx = threadIdx.x & 15, ty = threadIdx.x >> 4;
    #pragma unroll
    for (int i = 0; i < 4; i++) {
        const int m = m0 + (ty<<2) + i;
        float4 o;
        o.x = (acc[i][0] + bias[n0 + (tx<<2) + 0]) * scale;
        o.y = (acc[i][1] + bias[n0 + (tx<<2) + 1]) * scale;
        o.z = (acc[i][2] + bias[n0 + (tx<<2) + 2]) * scale;
        o.w = (acc[i][3] + bias[n0 + (tx<<2) + 3]) * scale;
        *(float4*)(out + (head * L + m) * HD + (tx<<2)) = o;
    }
}

// ---------------- kernel 2: causal Toeplitz conv, balanced chunks --------
// grid (40, 8, 2): x=task (lb,chunk), y=head, z=k/v. Each block <=4 s-tiles,
// writes a partial 64x64 tile to g_cpart[z][ch].
__global__ void __launch_bounds__(256)
conv_kernel(const float* __restrict__ phi)
{
    __shared__ float Ks[64*64];
    __shared__ float ph[128];
    int lb, ch;
    task_map(blockIdx.x, lb, ch);
    const int head = blockIdx.y;
    const int z    = blockIdx.z;
    const float* src = (z ? g_v : g_k) + head * L * HD;
    float* dst = g_cpart + (z * 4 + ch) * SZ + head * L * HD;

    const int tid = threadIdx.x;
    const int tx = tid & 15, ty = tid >> 4;
    const int l0 = lb * 64;
    const int sb_beg = ch * 4;
    const int sb_end = min(sb_beg + 4, lb + 1);
    float acc[4][4] = {};

    for (int sb = sb_beg; sb < sb_end; sb++) {
        const int s0 = sb * 64;
        #pragma unroll
        for (int rep = 0; rep < 4; rep++) {
            const int g  = tid + rep * 256;
            const int r  = g >> 4;
            const int c4 = (g & 15) << 2;
            *(float4*)(Ks + r*64 + c4) = *(const float4*)(src + (s0 + r) * HD + c4);
        }
        if (tid < 127) {
            const int off = l0 - s0 - 63 + tid;
            ph[tid] = (off >= 0) ? phi[off * H + head] : 0.0f;
        }
        __syncthreads();

        if (sb < lb) {
            #pragma unroll 4
            for (int s = 0; s < 64; s++) {
                float4 b4 = *(const float4*)(Ks + s*64 + (tx<<2));
                float b[4] = {b4.x, b4.y, b4.z, b4.w};
                #pragma unroll
                for (int i = 0; i < 4; i++) {
                    const float a = ph[63 + (ty<<2) + i - s];
                    #pragma unroll
                    for (int j = 0; j < 4; j++) acc[i][j] += a * b[j];
                }
            }
        } else {  // diagonal tile: causal mask l >= s
            #pragma unroll 4
            for (int s = 0; s < 64; s++) {
                float4 b4 = *(const float4*)(Ks + s*64 + (tx<<2));
                float b[4] = {b4.x, b4.y, b4.z, b4.w};
                #pragma unroll
                for (int i = 0; i < 4; i++) {
                    const int ll = (ty<<2) + i;
                    const float pv = ph[63 + ll - s];
                    const float a = (ll >= s) ? pv : 0.0f;
                    #pragma unroll
                    for (int j = 0; j < 4; j++) acc[i][j] += a * b[j];
                }
            }
        }
        __syncthreads();
    }

    #pragma unroll
    for (int i = 0; i < 4; i++) {
        float4 o = make_float4(acc[i][0], acc[i][1], acc[i][2], acc[i][3]);
        *(float4*)(dst + (l0 + (ty<<2) + i) * HD + (tx<<2)) = o;
    }
}

// ---------------- kernel 2b: conv finalize (sum <=4 partials) ------------
// grid (512, 2) x 256 threads; float4 elementwise.
__global__ void __launch_bounds__(256)
conv_fin_kernel()
{
    const int z = blockIdx.y;
    const int f = blockIdx.x * 256 + threadIdx.x;      // float4 index in [0, SZ/4)
    const int flat = f << 2;
    const int l = (flat >> 6) & (L - 1);
    const int n = (l >> 8) + 1;                        // #chunks covering row l
    const float* base = g_cpart + z * 4 * SZ;
    float4 s = ((const float4*)base)[f];
    for (int c = 1; c < n; c++) {
        float4 p = ((const float4*)(base + c * SZ))[f];
        s.x += p.x; s.y += p.y; s.z += p.z; s.w += p.w;
    }
    float* dst = z ? g_vc : g_kc;
    ((float4*)dst)[f] = s;
}

// ---------------- kernel 3: gates g = relu(v_c^T W k_c + b)^2 + eps ------
__global__ void __launch_bounds__(256)
gate_kernel(const float* __restrict__ wg, const float* __restrict__ wgb)
{
    __shared__ float wgT[64*64];
    const int tid = threadIdx.x;
    #pragma unroll
    for (int r = 0; r < 16; r++) {
        const int idx = tid + r * 256;
        const int m = idx >> 6, n = idx & 63;
        wgT[n * 64 + m] = wg[idx];
    }
    __syncthreads();

    const int warp = tid >> 5, lane = tid & 31;
    const int gidx = blockIdx.x * 8 + warp;      // = head*L + l
    const float* kc = g_kc + gidx * HD;
    const float* vc = g_vc + gidx * HD;

    float sum = 0.0f;
    #pragma unroll
    for (int half = 0; half < 2; half++) {
        const int m = lane + half * 32;
        float inner = 0.0f;
        #pragma unroll 8
        for (int n = 0; n < 64; n++)
            inner += wgT[n * 64 + m] * kc[n];
        sum += vc[m] * inner;
    }
    #pragma unroll
    for (int o = 16; o; o >>= 1) sum += __shfl_xor_sync(0xffffffffu, sum, o);

    if (lane == 0) {
        const float r = fmaxf(sum + wgb[0], 0.0f);
        g_gate[gidx] = r * r + EPSF;
    }
}

// ---------------- kernel 4: inclusive prefix sum of gates per head -------
__global__ void __launch_bounds__(1024)
scan_kernel()
{
    __shared__ float s[L];
    const int head = blockIdx.x, t = threadIdx.x;
    s[t] = g_gate[head * L + t];
    __syncthreads();
    for (int off = 1; off < L; off <<= 1) {
        const float v = (t >= off) ? s[t - off] : 0.0f;
        __syncthreads();
        s[t] += v;
        __syncthreads();
    }
    g_gcum[head * L + t] = s[t];
}

// ---------------- kernel 5: causal linear attention, balanced chunks -----
// grid (40, 8): x=task (lb,chunk), y=head. Partial O tile -> g_opart[ch].
__global__ void __launch_bounds__(256)
attn_kernel()
{
    __shared__ float QsT[64*64];   // Q transposed: [d][l]
    __shared__ float Ts [64*64];   // (g*Vc)^T [d][s], then Kc [s][d]
    __shared__ float Ps [64*64];   // P[l][s]

    int lb, ch;
    task_map(blockIdx.x, lb, ch);
    const int head = blockIdx.y;
    const int l0 = lb * 64;
    const float* qh  = g_q  + head * L * HD;
    const float* kch = g_kc + head * L * HD;
    const float* vch = g_vc + head * L * HD;
    const float* gh  = g_gate + head * L;

    const int tid = threadIdx.x;
    const int tx = tid & 15, ty = tid >> 4;

    #pragma unroll
    for (int rep = 0; rep < 4; rep++) {
        const int g  = tid + rep * 256;
        const int r  = g >> 4;
        const int c4 = (g & 15) << 2;
        float4 v = *(const float4*)(qh + (l0 + r) * HD + c4);
        QsT[(c4+0)*64 + r] = v.x;
        QsT[(c4+1)*64 + r] = v.y;
        QsT[(c4+2)*64 + r] = v.z;
        QsT[(c4+3)*64 + r] = v.w;
    }

    const int sb_beg = ch * 4;
    const int sb_end = min(sb_beg + 4, lb + 1);
    float acc[4][4] = {};
    for (int sb = sb_beg; sb < sb_end; sb++) {
        const int s0 = sb * 64;
        __syncthreads();
        #pragma unroll
        for (int rep = 0; rep < 4; rep++) {
            const int g  = tid + rep * 256;
            const int r  = g >> 4;
            const int c4 = (g & 15) << 2;
            const float gs = gh[s0 + r];
            float4 v = *(const float4*)(vch + (s0 + r) * HD + c4);
            Ts[(c4+0)*64 + r] = v.x * gs;
            Ts[(c4+1)*64 + r] = v.y * gs;
            Ts[(c4+2)*64 + r] = v.z * gs;
            Ts[(c4+3)*64 + r] = v.w * gs;
        }
        __syncthreads();

        float pacc[4][4] = {};
        #pragma unroll 4
        for (int dd = 0; dd < 64; dd++) {
            float4 a4 = *(const float4*)(QsT + dd*64 + (ty<<2));
            float4 b4 = *(const float4*)(Ts  + dd*64 + (tx<<2));
            float a[4] = {a4.x, a4.y, a4.z, a4.w};
            float b[4] = {b4.x, b4.y, b4.z, b4.w};
            #pragma unroll
            for (int i = 0; i < 4; i++)
                #pragma unroll
                for (int j = 0; j < 4; j++)
                    pacc[i][j] += a[i] * b[j];
        }
        if (sb == lb) {
            #pragma unroll
            for (int i = 0; i < 4; i++)
                #pragma unroll
                for (int j = 0; j < 4; j++)
                    if ((tx<<2) + j > (ty<<2) + i) pacc[i][j] = 0.0f;
        }
        #pragma unroll
        for (int i = 0; i < 4; i++)
            *(float4*)(Ps + ((ty<<2)+i)*64 + (tx<<2)) =
                make_float4(pacc[i][0], pacc[i][1], pacc[i][2], pacc[i][3]);
        __syncthreads();

        #pragma unroll
        for (int rep = 0; rep < 4; rep++) {
            const int g  = tid + rep * 256;
            const int r  = g >> 4;
            const int c4 = (g & 15) << 2;
            *(float4*)(Ts + r*64 + c4) = *(const float4*)(kch + (s0 + r) * HD + c4);
        }
        __syncthreads();

        #pragma unroll 4
        for (int s = 0; s < 64; s++) {
            float a[4];
            #pragma unroll
            for (int i = 0; i < 4; i++) a[i] = Ps[((ty<<2)+i)*64 + s];
            float4 b4 = *(const float4*)(Ts + s*64 + (tx<<2));
            float b[4] = {b4.x, b4.y, b4.z, b4.w};
            #pragma unroll
            for (int i = 0; i < 4; i++)
                #pragma unroll
                for (int j = 0; j < 4; j++)
                    acc[i][j] += a[i] * b[j];
        }
    }

    float* dst = g_opart + ch * SZ + head * L * HD;
    #pragma unroll
    for (int i = 0; i < 4; i++) {
        float4 o = make_float4(acc[i][0], acc[i][1], acc[i][2], acc[i][3]);
        *(float4*)(dst + (l0 + (ty<<2) + i) * HD + (tx<<2)) = o;
    }
}

// ---------------- kernel 5b: attn finalize -------------------------------
// Sum <=4 partials, scale by 1/(G+eps), L2-normalize each 64-row, write g_unit.
// One warp per (head,l): grid 1024 x 256.
__global__ void __launch_bounds__(256)
attn_fin_kernel()
{
    const int tid  = threadIdx.x;
    const int warp = tid >> 5, lane = tid & 31;
    const int row  = blockIdx.x * 8 + warp;          // head*L + l
    const int head = row >> 10;
    const int l    = row & (L - 1);
    const int n    = (l >> 8) + 1;                   // chunks for this lb

    const int d0 = lane * 2;
    const float* base = g_opart + row * HD + d0;
    float v0 = base[0], v1 = base[1];
    for (int c = 1; c < n; c++) {
        v0 += base[c * SZ + 0];
        v1 += base[c * SZ + 1];
    }
    const float gi = 1.0f / (g_gcum[row] + EPSF);
    v0 *= gi; v1 *= gi;

    float ss = v0 * v0 + v1 * v1;
    #pragma unroll
    for (int o = 16; o; o >>= 1) ss += __shfl_xor_sync(0xffffffffu, ss, o);
    const float ri = 1.0f / fmaxf(sqrtf(ss), EPSF);

    float2 o2 = make_float2(v0 * ri, v1 * ri);
    *(float2*)(g_unit + l * D + head * HD + d0) = o2;
}

// ---------------- kernel 6: output projection ----------------------------
__global__ void __launch_bounds__(256)
oproj_kernel(const float* __restrict__ wo, const float* __restrict__ bo,
             float* __restrict__ out)
{
    __shared__ float As[16*68];
    __shared__ float Bs[16*68];
    const int m0 = blockIdx.y * 64;
    const int n0 = blockIdx.x * 64;
    float acc[4][4] = {};
    gemm_acc(g_unit, wo, m0, n0, D, acc, As, Bs);

    const int tx = threadIdx.x & 15, ty = threadIdx.x >> 4;
    #pragma unroll
    for (int i = 0; i < 4; i++) {
        const int m = m0 + (ty<<2) + i;
        float4 o;
        o.x = acc[i][0] + bo[n0 + (tx<<2) + 0];
        o.y = acc[i][1] + bo[n0 + (tx<<2) + 1];
        o.z = acc[i][2] + bo[n0 + (tx<<2) + 2];
        o.w = acc[i][3] + bo[n0 + (tx<<2) + 3];
        *(float4*)(out + m * D + n0 + (tx<<2)) = o;
    }
}

// ---------------- launch --------------------------------------------------
extern "C" void kernel_launch(void* const* d_in, const int* in_sizes, int n_in,
                              void* d_out, int out_size)
{
    const float* x   = (const float*)d_in[0];
    const float* phi = (const float*)d_in[1];
    const float* wq  = (const float*)d_in[2];
    const float* bq  = (const float*)d_in[3];
    const float* wk  = (const float*)d_in[4];
    const float* bk  = (const float*)d_in[5];
    const float* wv  = (const float*)d_in[6];
    const float* bv  = (const float*)d_in[7];
    const float* wo  = (const float*)d_in[8];
    const float* bo  = (const float*)d_in[9];
    const float* wg  = (const float*)d_in[10];
    const float* wgb = (const float*)d_in[11];
    float* out = (float*)d_out;

    qkv_kernel     <<<dim3(8, 16, 3), 256>>>(x, wq, bq, wk, bk, wv, bv);
    conv_kernel    <<<dim3(40, 8, 2), 256>>>(phi);
    conv_fin_kernel<<<dim3(512, 2), 256>>>();
    gate_kernel    <<<1024, 256>>>(wg, wgb);
    scan_kernel    <<<8, 1024>>>();
    attn_kernel    <<<dim3(40, 8), 256>>>();
    attn_fin_kernel<<<1024, 256>>>();
    oproj_kernel   <<<dim3(8, 16), 256>>>(wo, bo, out);
}

// round 6
// speedup vs baseline: 1.3495x; 1.0947x over previous
#include <cuda_runtime.h>

#define L   1024
#define D   512
#define H   8
#define HD  64
#define EPSF 1e-5f
#define SZ  (H*L*HD)          // 524288 elems per [H][L][HD] tensor

// ---------------- scratch (device globals; no allocation) ----------------
__device__ float g_q [SZ];
__device__ float g_k [SZ];
__device__ float g_v [SZ];
__device__ float g_kc[SZ];
__device__ float g_vc[SZ];
__device__ float g_gate[H*L];
__device__ float g_gcum[H*L];
__device__ float g_unit[L*D];
__device__ float g_cpart[2*4*SZ];   // conv partials: [z][chunk][H][L][HD]
__device__ float g_opart[4*SZ];     // attn partials: [chunk][H][L][HD]

// Balanced triangular task map: 40 tasks per head, each <=4 s-tiles.
__device__ __forceinline__ void task_map(int t, int& lb, int& ch)
{
    int g, base;
    if      (t < 4)  { g = 0; base = 0;  }
    else if (t < 12) { g = 1; base = 4;  }
    else if (t < 24) { g = 2; base = 12; }
    else             { g = 3; base = 24; }
    const int idx = t - base;
    lb = g * 4 + idx / (g + 1);
    ch = idx % (g + 1);
}

// ---------------- shared 64x64x(K) GEMM core: C_tile = A @ B^T ----------
__device__ __forceinline__ void gemm_acc(const float* __restrict__ A,
                                         const float* __restrict__ B,
                                         int m0, int n0, int K,
                                         float acc[4][4],
                                         float* As, float* Bs)
{
    const int tid = threadIdx.x;
    const int tx = tid & 15, ty = tid >> 4;
    for (int k0 = 0; k0 < K; k0 += 16) {
        const int mr = tid >> 2;
        const int kq = (tid & 3) << 2;
        float4 av = *(const float4*)(A + (m0 + mr) * K + k0 + kq);
        As[(kq+0)*68 + mr] = av.x;
        As[(kq+1)*68 + mr] = av.y;
        As[(kq+2)*68 + mr] = av.z;
        As[(kq+3)*68 + mr] = av.w;
        float4 bv = *(const float4*)(B + (n0 + mr) * K + k0 + kq);
        Bs[(kq+0)*68 + mr] = bv.x;
        Bs[(kq+1)*68 + mr] = bv.y;
        Bs[(kq+2)*68 + mr] = bv.z;
        Bs[(kq+3)*68 + mr] = bv.w;
        __syncthreads();
        #pragma unroll
        for (int kk = 0; kk < 16; kk++) {
            float4 a4 = *(const float4*)(As + kk*68 + (ty<<2));
            float4 b4 = *(const float4*)(Bs + kk*68 + (tx<<2));
            float a[4] = {a4.x, a4.y, a4.z, a4.w};
            float b[4] = {b4.x, b4.y, b4.z, b4.w};
            #pragma unroll
            for (int i = 0; i < 4; i++)
                #pragma unroll
                for (int j = 0; j < 4; j++)
                    acc[i][j] += a[i] * b[j];
        }
        __syncthreads();
    }
}

// ---------------- kernel 1: fused QKV projections ------------------------
__global__ void __launch_bounds__(256)
qkv_kernel(const float* __restrict__ x,
           const float* __restrict__ wq, const float* __restrict__ bq,
           const float* __restrict__ wk, const float* __restrict__ bk,
           const float* __restrict__ wv, const float* __restrict__ bv)
{
    __shared__ float As[16*68];
    __shared__ float Bs[16*68];
    const int z = blockIdx.z;
    const float* W    = (z == 0) ? wq : (z == 1) ? wk : wv;
    const float* bias = (z == 0) ? bq : (z == 1) ? bk : bv;
    float* out        = (z == 0) ? g_q : (z == 1) ? g_k : g_v;
    const float scale = (z == 1) ? 0.125f : 1.0f;   // h^-0.5, h=64

    const int m0 = blockIdx.y * 64;
    const int n0 = blockIdx.x * 64;
    const int head = blockIdx.x;

    float acc[4][4] = {};
    gemm_acc(x, W, m0, n0, D, acc, As, Bs);

    const int tx = threadIdx.x & 15, ty = threadIdx.x >> 4;
    #pragma unroll
    for (int i = 0; i < 4; i++) {
        const int m = m0 + (ty<<2) + i;
        float4 o;
        o.x = (acc[i][0] + bias[n0 + (tx<<2) + 0]) * scale;
        o.y = (acc[i][1] + bias[n0 + (tx<<2) + 1]) * scale;
        o.z = (acc[i][2] + bias[n0 + (tx<<2) + 2]) * scale;
        o.w = (acc[i][3] + bias[n0 + (tx<<2) + 3]) * scale;
        *(float4*)(out + (head * L + m) * HD + (tx<<2)) = o;
    }
}

// ---------------- kernel 2: causal Toeplitz conv, balanced chunks --------
__global__ void __launch_bounds__(256)
conv_kernel(const float* __restrict__ phi)
{
    __shared__ float Ks[64*64];
    __shared__ float ph[128];
    int lb, ch;
    task_map(blockIdx.x, lb, ch);
    const int head = blockIdx.y;
    const int z    = blockIdx.z;
    const float* src = (z ? g_v : g_k) + head * L * HD;
    float* dst = g_cpart + (z * 4 + ch) * SZ + head * L * HD;

    const int tid = threadIdx.x;
    const int tx = tid & 15, ty = tid >> 4;
    const int l0 = lb * 64;
    const int sb_beg = ch * 4;
    const int sb_end = min(sb_beg + 4, lb + 1);
    float acc[4][4] = {};

    for (int sb = sb_beg; sb < sb_end; sb++) {
        const int s0 = sb * 64;
        #pragma unroll
        for (int rep = 0; rep < 4; rep++) {
            const int g  = tid + rep * 256;
            const int r  = g >> 4;
            const int c4 = (g & 15) << 2;
            *(float4*)(Ks + r*64 + c4) = *(const float4*)(src + (s0 + r) * HD + c4);
        }
        if (tid < 127) {
            const int off = l0 - s0 - 63 + tid;
            ph[tid] = (off >= 0) ? phi[off * H + head] : 0.0f;
        }
        __syncthreads();

        if (sb < lb) {
            #pragma unroll 4
            for (int s = 0; s < 64; s++) {
                float4 b4 = *(const float4*)(Ks + s*64 + (tx<<2));
                float b[4] = {b4.x, b4.y, b4.z, b4.w};
                #pragma unroll
                for (int i = 0; i < 4; i++) {
                    const float a = ph[63 + (ty<<2) + i - s];
                    #pragma unroll
                    for (int j = 0; j < 4; j++) acc[i][j] += a * b[j];
                }
            }
        } else {  // diagonal tile: causal mask l >= s
            #pragma unroll 4
            for (int s = 0; s < 64; s++) {
                float4 b4 = *(const float4*)(Ks + s*64 + (tx<<2));
                float b[4] = {b4.x, b4.y, b4.z, b4.w};
                #pragma unroll
                for (int i = 0; i < 4; i++) {
                    const int ll = (ty<<2) + i;
                    const float pv = ph[63 + ll - s];
                    const float a = (ll >= s) ? pv : 0.0f;
                    #pragma unroll
                    for (int j = 0; j < 4; j++) acc[i][j] += a * b[j];
                }
            }
        }
        __syncthreads();
    }

    #pragma unroll
    for (int i = 0; i < 4; i++) {
        float4 o = make_float4(acc[i][0], acc[i][1], acc[i][2], acc[i][3]);
        *(float4*)(dst + (l0 + (ty<<2) + i) * HD + (tx<<2)) = o;
    }
}

// ---------------- kernel 2b: conv finalize (sum <=4 partials) ------------
__global__ void __launch_bounds__(256)
conv_fin_kernel()
{
    const int z = blockIdx.y;
    const int f = blockIdx.x * 256 + threadIdx.x;      // float4 index in [0, SZ/4)
    const int flat = f << 2;
    const int l = (flat >> 6) & (L - 1);
    const int n = (l >> 8) + 1;                        // #chunks covering row l
    const float* base = g_cpart + z * 4 * SZ;
    float4 s = ((const float4*)base)[f];
    for (int c = 1; c < n; c++) {
        float4 p = ((const float4*)(base + c * SZ))[f];
        s.x += p.x; s.y += p.y; s.z += p.z; s.w += p.w;
    }
    float* dst = z ? g_vc : g_kc;
    ((float4*)dst)[f] = s;
}

// ---------------- kernel 3: gates, GEMM formulation ----------------------
// g[l] = relu( sum_m vc[l,m] * (Kc @ W^T)[l,m] + b )^2 + eps
// grid (16, 8): x = l-tile, y = head. 256 threads, 4x4 register tiles.
__global__ void __launch_bounds__(256)
gate_kernel(const float* __restrict__ wg, const float* __restrict__ wgb)
{
    __shared__ float sm[12288];         // 48KB: KsT | wgT | Vcs ; red aliases KsT
    float* KsT = sm;                    // [n][l] Kc transposed
    float* wgT = sm + 4096;             // [n][m] = wg[m*64+n]
    float* Vcs = sm + 8192;             // [l][m]

    const int lb = blockIdx.x, head = blockIdx.y;
    const int l0 = lb * 64;
    const float* kch = g_kc + (head * L + l0) * HD;
    const float* vch = g_vc + (head * L + l0) * HD;

    const int tid = threadIdx.x;
    const int tx = tid & 15, ty = tid >> 4;

    #pragma unroll
    for (int rep = 0; rep < 4; rep++) {
        const int g  = tid + rep * 256;
        const int r  = g >> 4;            // l (or m for wg)
        const int c4 = (g & 15) << 2;     // n
        float4 kv = *(const float4*)(kch + r * HD + c4);
        KsT[(c4+0)*64 + r] = kv.x;
        KsT[(c4+1)*64 + r] = kv.y;
        KsT[(c4+2)*64 + r] = kv.z;
        KsT[(c4+3)*64 + r] = kv.w;
        *(float4*)(Vcs + r*64 + c4) = *(const float4*)(vch + r * HD + c4);
        float4 wv = *(const float4*)(wg + r * 64 + c4);   // wg[m=r][n=c4..]
        wgT[(c4+0)*64 + r] = wv.x;
        wgT[(c4+1)*64 + r] = wv.y;
        wgT[(c4+2)*64 + r] = wv.z;
        wgT[(c4+3)*64 + r] = wv.w;
    }
    __syncthreads();

    // T[l][m] = sum_n kc[l,n] * W[m,n]
    float acc[4][4] = {};
    #pragma unroll 4
    for (int n = 0; n < 64; n++) {
        float4 a4 = *(const float4*)(KsT + n*64 + (ty<<2));
        float4 b4 = *(const float4*)(wgT + n*64 + (tx<<2));
        float a[4] = {a4.x, a4.y, a4.z, a4.w};
        float b[4] = {b4.x, b4.y, b4.z, b4.w};
        #pragma unroll
        for (int i = 0; i < 4; i++)
            #pragma unroll
            for (int j = 0; j < 4; j++)
                acc[i][j] += a[i] * b[j];
    }

    // psum[i] = sum_j T[l_i][m_j] * vc[l_i][m_j]
    float psum[4];
    #pragma unroll
    for (int i = 0; i < 4; i++) {
        float4 v4 = *(const float4*)(Vcs + ((ty<<2)+i)*64 + (tx<<2));
        psum[i] = acc[i][0]*v4.x + acc[i][1]*v4.y + acc[i][2]*v4.z + acc[i][3]*v4.w;
    }
    __syncthreads();                    // KsT no longer read
    float* red = KsT;                   // [64][16]
    #pragma unroll
    for (int i = 0; i < 4; i++)
        red[((ty<<2)+i)*16 + tx] = psum[i];
    __syncthreads();

    if (tid < 64) {
        float s = 0.0f;
        #pragma unroll
        for (int t = 0; t < 16; t++) s += red[tid*16 + t];
        const float r = fmaxf(s + wgb[0], 0.0f);
        g_gate[head * L + l0 + tid] = r * r + EPSF;
    }
}

// ---------------- kernel 4: inclusive prefix sum of gates per head -------
__global__ void __launch_bounds__(1024)
scan_kernel()
{
    __shared__ float s[L];
    const int head = blockIdx.x, t = threadIdx.x;
    s[t] = g_gate[head * L + t];
    __syncthreads();
    for (int off = 1; off < L; off <<= 1) {
        const float v = (t >= off) ? s[t - off] : 0.0f;
        __syncthreads();
        s[t] += v;
        __syncthreads();
    }
    g_gcum[head * L + t] = s[t];
}

// ---------------- kernel 5: causal linear attention, balanced chunks -----
__global__ void __launch_bounds__(256)
attn_kernel()
{
    __shared__ float QsT[64*64];   // Q transposed: [d][l]
    __shared__ float Ts [64*64];   // (g*Vc)^T [d][s], then Kc [s][d]
    __shared__ float Ps [64*64];   // P[l][s]

    int lb, ch;
    task_map(blockIdx.x, lb, ch);
    const int head = blockIdx.y;
    const int l0 = lb * 64;
    const float* qh  = g_q  + head * L * HD;
    const float* kch = g_kc + head * L * HD;
    const float* vch = g_vc + head * L * HD;
    const float* gh  = g_gate + head * L;

    const int tid = threadIdx.x;
    const int tx = tid & 15, ty = tid >> 4;

    #pragma unroll
    for (int rep = 0; rep < 4; rep++) {
        const int g  = tid + rep * 256;
        const int r  = g >> 4;
        const int c4 = (g & 15) << 2;
        float4 v = *(const float4*)(qh + (l0 + r) * HD + c4);
        QsT[(c4+0)*64 + r] = v.x;
        QsT[(c4+1)*64 + r] = v.y;
        QsT[(c4+2)*64 + r] = v.z;
        QsT[(c4+3)*64 + r] = v.w;
    }

    const int sb_beg = ch * 4;
    const int sb_end = min(sb_beg + 4, lb + 1);
    float acc[4][4] = {};
    for (int sb = sb_beg; sb < sb_end; sb++) {
        const int s0 = sb * 64;
        __syncthreads();
        #pragma unroll
        for (int rep = 0; rep < 4; rep++) {
            const int g  = tid + rep * 256;
            const int r  = g >> 4;
            const int c4 = (g & 15) << 2;
            const float gs = gh[s0 + r];
            float4 v = *(const float4*)(vch + (s0 + r) * HD + c4);
            Ts[(c4+0)*64 + r] = v.x * gs;
            Ts[(c4+1)*64 + r] = v.y * gs;
            Ts[(c4+2)*64 + r] = v.z * gs;
            Ts[(c4+3)*64 + r] = v.w * gs;
        }
        __syncthreads();

        float pacc[4][4] = {};
        #pragma unroll 4
        for (int dd = 0; dd < 64; dd++) {
            float4 a4 = *(const float4*)(QsT + dd*64 + (ty<<2));
            float4 b4 = *(const float4*)(Ts  + dd*64 + (tx<<2));
            float a[4] = {a4.x, a4.y, a4.z, a4.w};
            float b[4] = {b4.x, b4.y, b4.z, b4.w};
            #pragma unroll
            for (int i = 0; i < 4; i++)
                #pragma unroll
                for (int j = 0; j < 4; j++)
                    pacc[i][j] += a[i] * b[j];
        }
        if (sb == lb) {
            #pragma unroll
            for (int i = 0; i < 4; i++)
                #pragma unroll
                for (int j = 0; j < 4; j++)
                    if ((tx<<2) + j > (ty<<2) + i) pacc[i][j] = 0.0f;
        }
        #pragma unroll
        for (int i = 0; i < 4; i++)
            *(float4*)(Ps + ((ty<<2)+i)*64 + (tx<<2)) =
                make_float4(pacc[i][0], pacc[i][1], pacc[i][2], pacc[i][3]);
        __syncthreads();

        #pragma unroll
        for (int rep = 0; rep < 4; rep++) {
            const int g  = tid + rep * 256;
            const int r  = g >> 4;
            const int c4 = (g & 15) << 2;
            *(float4*)(Ts + r*64 + c4) = *(const float4*)(kch + (s0 + r) * HD + c4);
        }
        __syncthreads();

        #pragma unroll 4
        for (int s = 0; s < 64; s++) {
            float a[4];
            #pragma unroll
            for (int i = 0; i < 4; i++) a[i] = Ps[((ty<<2)+i)*64 + s];
            float4 b4 = *(const float4*)(Ts + s*64 + (tx<<2));
            float b[4] = {b4.x, b4.y, b4.z, b4.w};
            #pragma unroll
            for (int i = 0; i < 4; i++)
                #pragma unroll
                for (int j = 0; j < 4; j++)
                    acc[i][j] += a[i] * b[j];
        }
    }

    float* dst = g_opart + ch * SZ + head * L * HD;
    #pragma unroll
    for (int i = 0; i < 4; i++) {
        float4 o = make_float4(acc[i][0], acc[i][1], acc[i][2], acc[i][3]);
        *(float4*)(dst + (l0 + (ty<<2) + i) * HD + (tx<<2)) = o;
    }
}

// ---------------- kernel 5b: attn finalize -------------------------------
__global__ void __launch_bounds__(256)
attn_fin_kernel()
{
    const int tid  = threadIdx.x;
    const int warp = tid >> 5, lane = tid & 31;
    const int row  = blockIdx.x * 8 + warp;          // head*L + l
    const int head = row >> 10;
    const int l    = row & (L - 1);
    const int n    = (l >> 8) + 1;                   // chunks for this lb

    const int d0 = lane * 2;
    const float* base = g_opart + row * HD + d0;
    float v0 = base[0], v1 = base[1];
    for (int c = 1; c < n; c++) {
        v0 += base[c * SZ + 0];
        v1 += base[c * SZ + 1];
    }
    const float gi = 1.0f / (g_gcum[row] + EPSF);
    v0 *= gi; v1 *= gi;

    float ss = v0 * v0 + v1 * v1;
    #pragma unroll
    for (int o = 16; o; o >>= 1) ss += __shfl_xor_sync(0xffffffffu, ss, o);
    const float ri = 1.0f / fmaxf(sqrtf(ss), EPSF);

    float2 o2 = make_float2(v0 * ri, v1 * ri);
    *(float2*)(g_unit + l * D + head * HD + d0) = o2;
}

// ---------------- kernel 6: output projection ----------------------------
__global__ void __launch_bounds__(256)
oproj_kernel(const float* __restrict__ wo, const float* __restrict__ bo,
             float* __restrict__ out)
{
    __shared__ float As[16*68];
    __shared__ float Bs[16*68];
    const int m0 = blockIdx.y * 64;
    const int n0 = blockIdx.x * 64;
    float acc[4][4] = {};
    gemm_acc(g_unit, wo, m0, n0, D, acc, As, Bs);

    const int tx = threadIdx.x & 15, ty = threadIdx.x >> 4;
    #pragma unroll
    for (int i = 0; i < 4; i++) {
        const int m = m0 + (ty<<2) + i;
        float4 o;
        o.x = acc[i][0] + bo[n0 + (tx<<2) + 0];
        o.y = acc[i][1] + bo[n0 + (tx<<2) + 1];
        o.z = acc[i][2] + bo[n0 + (tx<<2) + 2];
        o.w = acc[i][3] + bo[n0 + (tx<<2) + 3];
        *(float4*)(out + m * D + n0 + (tx<<2)) = o;
    }
}

// ---------------- launch --------------------------------------------------
extern "C" void kernel_launch(void* const* d_in, const int* in_sizes, int n_in,
                              void* d_out, int out_size)
{
    const float* x   = (const float*)d_in[0];
    const float* phi = (const float*)d_in[1];
    const float* wq  = (const float*)d_in[2];
    const float* bq  = (const float*)d_in[3];
    const float* wk  = (const float*)d_in[4];
    const float* bk  = (const float*)d_in[5];
    const float* wv  = (const float*)d_in[6];
    const float* bv  = (const float*)d_in[7];
    const float* wo  = (const float*)d_in[8];
    const float* bo  = (const float*)d_in[9];
    const float* wg  = (const float*)d_in[10];
    const float* wgb = (const float*)d_in[11];
    float* out = (float*)d_out;

    qkv_kernel     <<<dim3(8, 16, 3), 256>>>(x, wq, bq, wk, bk, wv, bv);
    conv_kernel    <<<dim3(40, 8, 2), 256>>>(phi);
    conv_fin_kernel<<<dim3(512, 2), 256>>>();
    gate_kernel    <<<dim3(16, 8), 256>>>(wg, wgb);
    scan_kernel    <<<8, 1024>>>();
    attn_kernel    <<<dim3(40, 8), 256>>>();
    attn_fin_kernel<<<1024, 256>>>();
    oproj_kernel   <<<dim3(8, 16), 256>>>(wo, bo, out);
}

// round 7
// speedup vs baseline: 1.7571x; 1.3020x over previous
#include <cuda_runtime.h>

#define L   1024
#define D   512
#define H   8
#define HD  64
#define EPSF 1e-5f
#define SZ  (H*L*HD)          // 524288 elems per [H][L][HD] tensor

// ---------------- scratch (device globals; no allocation) ----------------
__device__ float g_q [SZ];
__device__ float g_k [SZ];
__device__ float g_v [SZ];
__device__ float g_kc[SZ];
__device__ float g_vc[SZ];
__device__ float g_gate[H*L];
__device__ float g_gcum[H*L];
__device__ float g_unit[L*D];
__device__ float g_cpart[2*4*SZ];   // conv partials: [z][chunk][H][L][HD]
__device__ float g_T[H*16*4096];    // per-tile state blocks T_j[m][n], [H][16][64][64]

// Balanced triangular task map: 40 tasks per head, each <=4 s-tiles.
__device__ __forceinline__ void task_map(int t, int& lb, int& ch)
{
    int g, base;
    if      (t < 4)  { g = 0; base = 0;  }
    else if (t < 12) { g = 1; base = 4;  }
    else if (t < 24) { g = 2; base = 12; }
    else             { g = 3; base = 24; }
    const int idx = t - base;
    lb = g * 4 + idx / (g + 1);
    ch = idx % (g + 1);
}

// ---------------- shared 64x64x(K) GEMM core: C_tile = A @ B^T ----------
__device__ __forceinline__ void gemm_acc(const float* __restrict__ A,
                                         const float* __restrict__ B,
                                         int m0, int n0, int K,
                                         float acc[4][4],
                                         float* As, float* Bs)
{
    const int tid = threadIdx.x;
    const int tx = tid & 15, ty = tid >> 4;
    for (int k0 = 0; k0 < K; k0 += 16) {
        const int mr = tid >> 2;
        const int kq = (tid & 3) << 2;
        float4 av = *(const float4*)(A + (m0 + mr) * K + k0 + kq);
        As[(kq+0)*68 + mr] = av.x;
        As[(kq+1)*68 + mr] = av.y;
        As[(kq+2)*68 + mr] = av.z;
        As[(kq+3)*68 + mr] = av.w;
        float4 bv = *(const float4*)(B + (n0 + mr) * K + k0 + kq);
        Bs[(kq+0)*68 + mr] = bv.x;
        Bs[(kq+1)*68 + mr] = bv.y;
        Bs[(kq+2)*68 + mr] = bv.z;
        Bs[(kq+3)*68 + mr] = bv.w;
        __syncthreads();
        #pragma unroll
        for (int kk = 0; kk < 16; kk++) {
            float4 a4 = *(const float4*)(As + kk*68 + (ty<<2));
            float4 b4 = *(const float4*)(Bs + kk*68 + (tx<<2));
            float a[4] = {a4.x, a4.y, a4.z, a4.w};
            float b[4] = {b4.x, b4.y, b4.z, b4.w};
            #pragma unroll
            for (int i = 0; i < 4; i++)
                #pragma unroll
                for (int j = 0; j < 4; j++)
                    acc[i][j] += a[i] * b[j];
        }
        __syncthreads();
    }
}

// ---------------- kernel 1: fused QKV projections ------------------------
__global__ void __launch_bounds__(256)
qkv_kernel(const float* __restrict__ x,
           const float* __restrict__ wq, const float* __restrict__ bq,
           const float* __restrict__ wk, const float* __restrict__ bk,
           const float* __restrict__ wv, const float* __restrict__ bv)
{
    __shared__ float As[16*68];
    __shared__ float Bs[16*68];
    const int z = blockIdx.z;
    const float* W    = (z == 0) ? wq : (z == 1) ? wk : wv;
    const float* bias = (z == 0) ? bq : (z == 1) ? bk : bv;
    float* out        = (z == 0) ? g_q : (z == 1) ? g_k : g_v;
    const float scale = (z == 1) ? 0.125f : 1.0f;   // h^-0.5, h=64

    const int m0 = blockIdx.y * 64;
    const int n0 = blockIdx.x * 64;
    const int head = blockIdx.x;

    float acc[4][4] = {};
    gemm_acc(x, W, m0, n0, D, acc, As, Bs);

    const int tx = threadIdx.x & 15, ty = threadIdx.x >> 4;
    #pragma unroll
    for (int i = 0; i < 4; i++) {
        const int m = m0 + (ty<<2) + i;
        float4 o;
        o.x = (acc[i][0] + bias[n0 + (tx<<2) + 0]) * scale;
        o.y = (acc[i][1] + bias[n0 + (tx<<2) + 1]) * scale;
        o.z = (acc[i][2] + bias[n0 + (tx<<2) + 2]) * scale;
        o.w = (acc[i][3] + bias[n0 + (tx<<2) + 3]) * scale;
        *(float4*)(out + (head * L + m) * HD + (tx<<2)) = o;
    }
}

// ---------------- kernel 2: causal Toeplitz conv, balanced chunks --------
__global__ void __launch_bounds__(256)
conv_kernel(const float* __restrict__ phi)
{
    __shared__ float Ks[64*64];
    __shared__ float ph[128];
    int lb, ch;
    task_map(blockIdx.x, lb, ch);
    const int head = blockIdx.y;
    const int z    = blockIdx.z;
    const float* src = (z ? g_v : g_k) + head * L * HD;
    float* dst = g_cpart + (z * 4 + ch) * SZ + head * L * HD;

    const int tid = threadIdx.x;
    const int tx = tid & 15, ty = tid >> 4;
    const int l0 = lb * 64;
    const int sb_beg = ch * 4;
    const int sb_end = min(sb_beg + 4, lb + 1);
    float acc[4][4] = {};

    for (int sb = sb_beg; sb < sb_end; sb++) {
        const int s0 = sb * 64;
        #pragma unroll
        for (int rep = 0; rep < 4; rep++) {
            const int g  = tid + rep * 256;
            const int r  = g >> 4;
            const int c4 = (g & 15) << 2;
            *(float4*)(Ks + r*64 + c4) = *(const float4*)(src + (s0 + r) * HD + c4);
        }
        if (tid < 127) {
            const int off = l0 - s0 - 63 + tid;
            ph[tid] = (off >= 0) ? phi[off * H + head] : 0.0f;
        }
        __syncthreads();

        if (sb < lb) {
            #pragma unroll 4
            for (int s = 0; s < 64; s++) {
                float4 b4 = *(const float4*)(Ks + s*64 + (tx<<2));
                float b[4] = {b4.x, b4.y, b4.z, b4.w};
                #pragma unroll
                for (int i = 0; i < 4; i++) {
                    const float a = ph[63 + (ty<<2) + i - s];
                    #pragma unroll
                    for (int j = 0; j < 4; j++) acc[i][j] += a * b[j];
                }
            }
        } else {  // diagonal tile: causal mask l >= s
            #pragma unroll 4
            for (int s = 0; s < 64; s++) {
                float4 b4 = *(const float4*)(Ks + s*64 + (tx<<2));
                float b[4] = {b4.x, b4.y, b4.z, b4.w};
                #pragma unroll
                for (int i = 0; i < 4; i++) {
                    const int ll = (ty<<2) + i;
                    const float pv = ph[63 + ll - s];
                    const float a = (ll >= s) ? pv : 0.0f;
                    #pragma unroll
                    for (int j = 0; j < 4; j++) acc[i][j] += a * b[j];
                }
            }
        }
        __syncthreads();
    }

    #pragma unroll
    for (int i = 0; i < 4; i++) {
        float4 o = make_float4(acc[i][0], acc[i][1], acc[i][2], acc[i][3]);
        *(float4*)(dst + (l0 + (ty<<2) + i) * HD + (tx<<2)) = o;
    }
}

// ---------------- kernel 2b: conv finalize (sum <=4 partials) ------------
__global__ void __launch_bounds__(256)
conv_fin_kernel()
{
    const int z = blockIdx.y;
    const int f = blockIdx.x * 256 + threadIdx.x;      // float4 index in [0, SZ/4)
    const int flat = f << 2;
    const int l = (flat >> 6) & (L - 1);
    const int n = (l >> 8) + 1;                        // #chunks covering row l
    const float* base = g_cpart + z * 4 * SZ;
    float4 s = ((const float4*)base)[f];
    for (int c = 1; c < n; c++) {
        float4 p = ((const float4*)(base + c * SZ))[f];
        s.x += p.x; s.y += p.y; s.z += p.z; s.w += p.w;
    }
    float* dst = z ? g_vc : g_kc;
    ((float4*)dst)[f] = s;
}

// ---------------- kernel 3: gates + per-tile state block T_j -------------
// Phase A: g[l] = relu( sum_m vc[l,m] * (Kc @ W^T)[l,m] + b )^2 + eps
// Phase B: T_j[m][n] = sum_{s in tile} g_s * vc[s,m] * kc[s,n]
// grid (16, 8): x = l-tile j, y = head. 256 threads.
__global__ void __launch_bounds__(256)
gate_kernel(const float* __restrict__ wg, const float* __restrict__ wgb)
{
    __shared__ float sm[12288];         // 48KB
    float* KsT   = sm;                  // [n][l] Kc transposed (phase A)
    float* wgT   = sm + 4096;           // [n][m]; phase B: Ksn [s][n]
    float* Vcs   = sm + 8192;           // [s][m]
    float* red   = sm;                  // alias: [64][16] reduction (after A reads)
    float* gvals = sm + 1536;           // alias: 64 gate values

    const int lb = blockIdx.x, head = blockIdx.y;
    const int l0 = lb * 64;
    const float* kch = g_kc + (head * L + l0) * HD;
    const float* vch = g_vc + (head * L + l0) * HD;

    const int tid = threadIdx.x;
    const int tx = tid & 15, ty = tid >> 4;

    #pragma unroll
    for (int rep = 0; rep < 4; rep++) {
        const int g  = tid + rep * 256;
        const int r  = g >> 4;            // l (or m for wg)
        const int c4 = (g & 15) << 2;     // n
        float4 kv = *(const float4*)(kch + r * HD + c4);
        KsT[(c4+0)*64 + r] = kv.x;
        KsT[(c4+1)*64 + r] = kv.y;
        KsT[(c4+2)*64 + r] = kv.z;
        KsT[(c4+3)*64 + r] = kv.w;
        *(float4*)(Vcs + r*64 + c4) = *(const float4*)(vch + r * HD + c4);
        float4 wv = *(const float4*)(wg + r * 64 + c4);   // wg[m=r][n=c4..]
        wgT[(c4+0)*64 + r] = wv.x;
        wgT[(c4+1)*64 + r] = wv.y;
        wgT[(c4+2)*64 + r] = wv.z;
        wgT[(c4+3)*64 + r] = wv.w;
    }
    __syncthreads();

    // Phase A: Tg[l][m] = sum_n kc[l,n] * W[m,n]; psum = <Tg[l], vc[l]>
    float acc[4][4] = {};
    #pragma unroll 4
    for (int n = 0; n < 64; n++) {
        float4 a4 = *(const float4*)(KsT + n*64 + (ty<<2));
        float4 b4 = *(const float4*)(wgT + n*64 + (tx<<2));
        float a[4] = {a4.x, a4.y, a4.z, a4.w};
        float b[4] = {b4.x, b4.y, b4.z, b4.w};
        #pragma unroll
        for (int i = 0; i < 4; i++)
            #pragma unroll
            for (int j = 0; j < 4; j++)
                acc[i][j] += a[i] * b[j];
    }
    float psum[4];
    #pragma unroll
    for (int i = 0; i < 4; i++) {
        float4 v4 = *(const float4*)(Vcs + ((ty<<2)+i)*64 + (tx<<2));
        psum[i] = acc[i][0]*v4.x + acc[i][1]*v4.y + acc[i][2]*v4.z + acc[i][3]*v4.w;
    }
    __syncthreads();                    // KsT/wgT reads done
    #pragma unroll
    for (int i = 0; i < 4; i++)
        red[((ty<<2)+i)*16 + tx] = psum[i];
    __syncthreads();

    if (tid < 64) {
        float s = 0.0f;
        #pragma unroll
        for (int t = 0; t < 16; t++) s += red[tid*16 + t];
        const float r = fmaxf(s + wgb[0], 0.0f);
        const float gv = r * r + EPSF;
        g_gate[head * L + l0 + tid] = gv;
        gvals[tid] = gv;
    }
    __syncthreads();

    // Phase B: reload Kc natural into wgT area; scale Vcs rows by g.
    float* Ksn = wgT;
    #pragma unroll
    for (int rep = 0; rep < 4; rep++) {
        const int g  = tid + rep * 256;
        const int r  = g >> 4;
        const int c4 = (g & 15) << 2;
        *(float4*)(Ksn + r*64 + c4) = *(const float4*)(kch + r * HD + c4);
    }
    #pragma unroll
    for (int k = 0; k < 4; k++) {
        const int f = tid + k * 256;          // float4 idx; s = f>>4
        const float gv = gvals[f >> 4];
        float4 v = ((float4*)Vcs)[f];
        v.x *= gv; v.y *= gv; v.z *= gv; v.w *= gv;
        ((float4*)Vcs)[f] = v;
    }
    __syncthreads();

    // T[m][n] = sum_s gVcs[s][m] * Ksn[s][n]
    float tacc[4][4] = {};
    #pragma unroll 4
    for (int s = 0; s < 64; s++) {
        float4 a4 = *(const float4*)(Vcs + s*64 + (ty<<2));
        float4 b4 = *(const float4*)(Ksn + s*64 + (tx<<2));
        float a[4] = {a4.x, a4.y, a4.z, a4.w};
        float b[4] = {b4.x, b4.y, b4.z, b4.w};
        #pragma unroll
        for (int i = 0; i < 4; i++)
            #pragma unroll
            for (int j = 0; j < 4; j++)
                tacc[i][j] += a[i] * b[j];
    }
    float* dst = g_T + (head * 16 + lb) * 4096;
    #pragma unroll
    for (int i = 0; i < 4; i++)
        *(float4*)(dst + ((ty<<2)+i)*64 + (tx<<2)) =
            make_float4(tacc[i][0], tacc[i][1], tacc[i][2], tacc[i][3]);
}

// ---------------- kernel 4: inclusive prefix sum of gates per head -------
__global__ void __launch_bounds__(1024)
scan_kernel()
{
    __shared__ float s[L];
    const int head = blockIdx.x, t = threadIdx.x;
    s[t] = g_gate[head * L + t];
    __syncthreads();
    for (int off = 1; off < L; off <<= 1) {
        const float v = (t >= off) ? s[t - off] : 0.0f;
        __syncthreads();
        s[t] += v;
        __syncthreads();
    }
    g_gcum[head * L + t] = s[t];
}

// ---------------- kernel 5: chunked-state attention + normalize ----------
// ctxt_j = Q_j @ S_{j-1} + causal_intra(Q_j, g*Vc_j, Kc_j); S = prefix of T.
// grid (16, 8): x = tile j, y = head. 48KB smem, fused epilogue.
__global__ void __launch_bounds__(256)
ctxt_kernel()
{
    __shared__ float sm[12288];
    float* QsT = sm;          // [d][l]
    float* Sb  = sm + 4096;   // S [d][o]; later P [l][s]; later ctxt [l][o]
    float* Xb  = sm + 8192;   // gVcT [d][s]; later Kc [s][o]; later row norms

    const int j = blockIdx.x, head = blockIdx.y;
    const int l0 = j * 64;
    const float* qh  = g_q  + (head * L + l0) * HD;
    const float* kch = g_kc + (head * L + l0) * HD;
    const float* vch = g_vc + (head * L + l0) * HD;
    const float* gh  = g_gate + head * L + l0;

    const int tid = threadIdx.x;
    const int tx = tid & 15, ty = tid >> 4;

    // load Q transposed; load gVc transposed; accumulate S prefix in regs
    #pragma unroll
    for (int rep = 0; rep < 4; rep++) {
        const int g  = tid + rep * 256;
        const int r  = g >> 4;            // l / s
        const int c4 = (g & 15) << 2;     // d
        float4 q4 = *(const float4*)(qh + r * HD + c4);
        QsT[(c4+0)*64 + r] = q4.x;
        QsT[(c4+1)*64 + r] = q4.y;
        QsT[(c4+2)*64 + r] = q4.z;
        QsT[(c4+3)*64 + r] = q4.w;
        const float gs = gh[r];
        float4 v4 = *(const float4*)(vch + r * HD + c4);
        Xb[(c4+0)*64 + r] = v4.x * gs;
        Xb[(c4+1)*64 + r] = v4.y * gs;
        Xb[(c4+2)*64 + r] = v4.z * gs;
        Xb[(c4+3)*64 + r] = v4.w * gs;
    }
    {
        float4 sacc0 = make_float4(0.f,0.f,0.f,0.f), sacc1 = sacc0,
               sacc2 = sacc0, sacc3 = sacc0;
        const float4* tbase = (const float4*)(g_T + head * 16 * 4096);
        for (int i = 0; i < j; i++) {
            const float4* tp = tbase + i * 1024;
            float4 p;
            p = tp[tid +   0]; sacc0.x += p.x; sacc0.y += p.y; sacc0.z += p.z; sacc0.w += p.w;
            p = tp[tid + 256]; sacc1.x += p.x; sacc1.y += p.y; sacc1.z += p.z; sacc1.w += p.w;
            p = tp[tid + 512]; sacc2.x += p.x; sacc2.y += p.y; sacc2.z += p.z; sacc2.w += p.w;
            p = tp[tid + 768]; sacc3.x += p.x; sacc3.y += p.y; sacc3.z += p.z; sacc3.w += p.w;
        }
        ((float4*)Sb)[tid +   0] = sacc0;
        ((float4*)Sb)[tid + 256] = sacc1;
        ((float4*)Sb)[tid + 512] = sacc2;
        ((float4*)Sb)[tid + 768] = sacc3;
    }
    __syncthreads();

    // ctxt1: acc[l][o] = sum_d q[l,d] * S[d,o]
    float acc[4][4] = {};
    if (j > 0) {
        #pragma unroll 4
        for (int d = 0; d < 64; d++) {
            float4 a4 = *(const float4*)(QsT + d*64 + (ty<<2));
            float4 b4 = *(const float4*)(Sb  + d*64 + (tx<<2));
            float a[4] = {a4.x, a4.y, a4.z, a4.w};
            float b[4] = {b4.x, b4.y, b4.z, b4.w};
            #pragma unroll
            for (int i = 0; i < 4; i++)
                #pragma unroll
                for (int jj = 0; jj < 4; jj++)
                    acc[i][jj] += a[i] * b[jj];
        }
    }

    // intra stage 1: P[l][s] = sum_d q[l,d] * gv[s,d], masked s<=l
    float pacc[4][4] = {};
    #pragma unroll 4
    for (int d = 0; d < 64; d++) {
        float4 a4 = *(const float4*)(QsT + d*64 + (ty<<2));
        float4 b4 = *(const float4*)(Xb  + d*64 + (tx<<2));
        float a[4] = {a4.x, a4.y, a4.z, a4.w};
        float b[4] = {b4.x, b4.y, b4.z, b4.w};
        #pragma unroll
        for (int i = 0; i < 4; i++)
            #pragma unroll
            for (int jj = 0; jj < 4; jj++)
                pacc[i][jj] += a[i] * b[jj];
    }
    #pragma unroll
    for (int i = 0; i < 4; i++)
        #pragma unroll
        for (int jj = 0; jj < 4; jj++)
            if ((tx<<2) + jj > (ty<<2) + i) pacc[i][jj] = 0.0f;
    __syncthreads();                    // Sb/Xb reads done

    // store P into Sb; load Kc into Xb
    #pragma unroll
    for (int i = 0; i < 4; i++)
        *(float4*)(Sb + ((ty<<2)+i)*64 + (tx<<2)) =
            make_float4(pacc[i][0], pacc[i][1], pacc[i][2], pacc[i][3]);
    #pragma unroll
    for (int rep = 0; rep < 4; rep++) {
        const int g  = tid + rep * 256;
        const int r  = g >> 4;
        const int c4 = (g & 15) << 2;
        *(float4*)(Xb + r*64 + c4) = *(const float4*)(kch + r * HD + c4);
    }
    __syncthreads();

    // intra stage 2: acc[l][o] += sum_s P[l,s] * kc[s,o]
    #pragma unroll 4
    for (int s = 0; s < 64; s++) {
        float a[4];
        #pragma unroll
        for (int i = 0; i < 4; i++) a[i] = Sb[((ty<<2)+i)*64 + s];
        float4 b4 = *(const float4*)(Xb + s*64 + (tx<<2));
        float b[4] = {b4.x, b4.y, b4.z, b4.w};
        #pragma unroll
        for (int i = 0; i < 4; i++)
            #pragma unroll
            for (int jj = 0; jj < 4; jj++)
                acc[i][jj] += a[i] * b[jj];
    }
    __syncthreads();                    // Sb reads done

    // epilogue: /(G+eps), row L2 normalize, write g_unit
    #pragma unroll
    for (int i = 0; i < 4; i++) {
        const float G = g_gcum[head * L + l0 + (ty<<2) + i];
        const float gi = 1.0f / (G + EPSF);
        #pragma unroll
        for (int jj = 0; jj < 4; jj++) acc[i][jj] *= gi;
        *(float4*)(Sb + ((ty<<2)+i)*64 + (tx<<2)) =
            make_float4(acc[i][0], acc[i][1], acc[i][2], acc[i][3]);
    }
    __syncthreads();

    if (tid < 64) {
        float ss = 0.0f;
        #pragma unroll 8
        for (int d2 = 0; d2 < 64; d2++) {
            const float c = Sb[tid*64 + d2];
            ss += c * c;
        }
        Xb[tid] = fmaxf(sqrtf(ss), EPSF);
    }
    __syncthreads();

    #pragma unroll
    for (int i = 0; i < 4; i++) {
        const float ri = 1.0f / Xb[(ty<<2) + i];
        float4 o = make_float4(acc[i][0]*ri, acc[i][1]*ri, acc[i][2]*ri, acc[i][3]*ri);
        *(float4*)(g_unit + (l0 + (ty<<2) + i) * D + head * HD + (tx<<2)) = o;
    }
}

// ---------------- kernel 6: output projection ----------------------------
__global__ void __launch_bounds__(256)
oproj_kernel(const float* __restrict__ wo, const float* __restrict__ bo,
             float* __restrict__ out)
{
    __shared__ float As[16*68];
    __shared__ float Bs[16*68];
    const int m0 = blockIdx.y * 64;
    const int n0 = blockIdx.x * 64;
    float acc[4][4] = {};
    gemm_acc(g_unit, wo, m0, n0, D, acc, As, Bs);

    const int tx = threadIdx.x & 15, ty = threadIdx.x >> 4;
    #pragma unroll
    for (int i = 0; i < 4; i++) {
        const int m = m0 + (ty<<2) + i;
        float4 o;
        o.x = acc[i][0] + bo[n0 + (tx<<2) + 0];
        o.y = acc[i][1] + bo[n0 + (tx<<2) + 1];
        o.z = acc[i][2] + bo[n0 + (tx<<2) + 2];
        o.w = acc[i][3] + bo[n0 + (tx<<2) + 3];
        *(float4*)(out + m * D + n0 + (tx<<2)) = o;
    }
}

// ---------------- launch --------------------------------------------------
extern "C" void kernel_launch(void* const* d_in, const int* in_sizes, int n_in,
                              void* d_out, int out_size)
{
    const float* x   = (const float*)d_in[0];
    const float* phi = (const float*)d_in[1];
    const float* wq  = (const float*)d_in[2];
    const float* bq  = (const float*)d_in[3];
    const float* wk  = (const float*)d_in[4];
    const float* bk  = (const float*)d_in[5];
    const float* wv  = (const float*)d_in[6];
    const float* bv  = (const float*)d_in[7];
    const float* wo  = (const float*)d_in[8];
    const float* bo  = (const float*)d_in[9];
    const float* wg  = (const float*)d_in[10];
    const float* wgb = (const float*)d_in[11];
    float* out = (float*)d_out;

    qkv_kernel     <<<dim3(8, 16, 3), 256>>>(x, wq, bq, wk, bk, wv, bv);
    conv_kernel    <<<dim3(40, 8, 2), 256>>>(phi);
    conv_fin_kernel<<<dim3(512, 2), 256>>>();
    gate_kernel    <<<dim3(16, 8), 256>>>(wg, wgb);
    scan_kernel    <<<8, 1024>>>();
    ctxt_kernel    <<<dim3(16, 8), 256>>>();
    oproj_kernel   <<<dim3(8, 16), 256>>>(wo, bo, out);
}